// round 2
// baseline (speedup 1.0000x reference)
#include <cuda_runtime.h>
#include <cuda_bf16.h>

#define N_NODES 10000
#define DIM     256
#define E_MAX   320000

#define MIN_NORM 1e-15f
#define MAXNORM  0.996f   // (1 - 4e-3)/sqrt(c), c = 1

// ---------------- device scratch (no allocations allowed) ----------------
__device__ float g_h [N_NODES * DIM];
__device__ float g_mx[N_NODES * DIM];
__device__ float g_xt[N_NODES * DIM];
__device__ int   g_cnt[N_NODES];
__device__ int   g_rowptr[N_NODES + 1];
__device__ int   g_cursor[N_NODES];
__device__ int   g_ssrc[E_MAX];
__device__ float g_sw[E_MAX];
__device__ float g_bias[2][DIM];

// ---------------- helpers ----------------
__device__ __forceinline__ float artanh_clip(float x) {
    x = fminf(fmaxf(x, -1.0f + 1e-7f), 1.0f - 1e-7f);
    return atanhf(x);
}

__device__ __forceinline__ float bsum256(float v, float* red) {
    #pragma unroll
    for (int o = 16; o > 0; o >>= 1) v += __shfl_xor_sync(0xffffffffu, v, o);
    if ((threadIdx.x & 31) == 0) red[threadIdx.x >> 5] = v;
    __syncthreads();
    float r = red[0] + red[1] + red[2] + red[3] + red[4] + red[5] + red[6] + red[7];
    __syncthreads();
    return r;
}

// ---------------- CSR build ----------------
__global__ void zero_cnt_k(int n) {
    int i = blockIdx.x * blockDim.x + threadIdx.x;
    if (i < n) g_cnt[i] = 0;
}

__global__ void hist_k(const int* __restrict__ dst, int E) {
    int e = blockIdx.x * blockDim.x + threadIdx.x;
    if (e < E) atomicAdd(&g_cnt[dst[e]], 1);
}

__global__ void scan_k(int n) {
    __shared__ int warp_sums[32];
    __shared__ int s_off;
    int t = threadIdx.x, lane = t & 31, wid = t >> 5;
    if (t == 0) s_off = 0;
    __syncthreads();
    for (int base = 0; base < n; base += 1024) {
        int i = base + t;
        int v = (i < n) ? g_cnt[i] : 0;
        int x = v;
        #pragma unroll
        for (int o = 1; o < 32; o <<= 1) {
            int y = __shfl_up_sync(0xffffffffu, x, o);
            if (lane >= o) x += y;
        }
        if (lane == 31) warp_sums[wid] = x;
        __syncthreads();
        if (wid == 0) {
            int w = warp_sums[lane];
            #pragma unroll
            for (int o = 1; o < 32; o <<= 1) {
                int y = __shfl_up_sync(0xffffffffu, w, o);
                if (lane >= o) w += y;
            }
            warp_sums[lane] = w;
        }
        __syncthreads();
        int warp_off = (wid > 0) ? warp_sums[wid - 1] : 0;
        int incl = x + warp_off;
        int excl = incl - v;
        int off  = s_off;
        if (i < n) { g_rowptr[i] = off + excl; g_cursor[i] = off + excl; }
        __syncthreads();
        if (t == 1023) s_off = off + incl;
        __syncthreads();
    }
    if (t == 0) g_rowptr[n] = s_off;
}

__global__ void fill_k(const int* __restrict__ src, const int* __restrict__ dst,
                       const float* __restrict__ w, int E) {
    int e = blockIdx.x * blockDim.x + threadIdx.x;
    if (e < E) {
        int p = atomicAdd(&g_cursor[dst[e]], 1);
        g_ssrc[p] = src[e];
        g_sw[p]   = w[e];
    }
}

// ---------------- hyp_bias = proj(expmap0(b)) ----------------
__global__ void bias_k(const float* __restrict__ b1, const float* __restrict__ b2) {
    __shared__ float red[8];
    const float* b = blockIdx.x ? b2 : b1;
    int t = threadIdx.x;
    float v = b[t];
    float s = bsum256(v * v, red);
    float n = fmaxf(sqrtf(s), MIN_NORM);
    v *= tanhf(n) / n;                         // expmap0
    s = bsum256(v * v, red);
    n = fmaxf(sqrtf(s), MIN_NORM);
    if (n > MAXNORM) v *= MAXNORM / n;         // proj
    g_bias[blockIdx.x][t] = v;
}

// ---------------- h0 = proj(expmap0(x)) ----------------
__global__ void init_k(const float* __restrict__ x) {
    __shared__ float red[8];
    int i = blockIdx.x, t = threadIdx.x;
    float v = x[i * DIM + t];
    float s = bsum256(v * v, red);
    float n = fmaxf(sqrtf(s), MIN_NORM);
    v *= tanhf(n) / n;
    s = bsum256(v * v, red);
    n = fmaxf(sqrtf(s), MIN_NORM);
    if (n > MAXNORM) v *= MAXNORM / n;
    g_h[i * DIM + t] = v;
}

// ---------------- GEMM: g_mx = g_h @ W^T  (NT, fp32) ----------------
#define BM 128
#define BN 64
#define BK 16
__global__ __launch_bounds__(256) void gemm_k(const float* __restrict__ W, int M) {
    __shared__ float As[BK][BM];
    __shared__ float Bs[BK][BN];
    int tid = threadIdx.x;
    int bm = blockIdx.x * BM;
    int bn = blockIdx.y * BN;
    int tx = tid & 15;
    int ty = tid >> 4;
    int lr = tid >> 2;
    int lk = (tid & 3) << 2;

    float acc[8][4];
    #pragma unroll
    for (int i = 0; i < 8; i++)
        #pragma unroll
        for (int j = 0; j < 4; j++) acc[i][j] = 0.0f;

    for (int k0 = 0; k0 < DIM; k0 += BK) {
        #pragma unroll
        for (int h = 0; h < 2; h++) {
            int r = bm + lr + h * 64;
            float4 v = (r < M) ? *(const float4*)&g_h[(size_t)r * DIM + k0 + lk]
                               : make_float4(0.f, 0.f, 0.f, 0.f);
            As[lk + 0][lr + h * 64] = v.x;
            As[lk + 1][lr + h * 64] = v.y;
            As[lk + 2][lr + h * 64] = v.z;
            As[lk + 3][lr + h * 64] = v.w;
        }
        {
            float4 v = *(const float4*)&W[(size_t)(bn + lr) * DIM + k0 + lk];
            Bs[lk + 0][lr] = v.x;
            Bs[lk + 1][lr] = v.y;
            Bs[lk + 2][lr] = v.z;
            Bs[lk + 3][lr] = v.w;
        }
        __syncthreads();
        #pragma unroll
        for (int k = 0; k < BK; k++) {
            float4 b  = *(const float4*)&Bs[k][tx * 4];
            float4 a0 = *(const float4*)&As[k][ty * 8];
            float4 a1 = *(const float4*)&As[k][ty * 8 + 4];
            float av[8] = {a0.x, a0.y, a0.z, a0.w, a1.x, a1.y, a1.z, a1.w};
            float bv[4] = {b.x, b.y, b.z, b.w};
            #pragma unroll
            for (int i = 0; i < 8; i++)
                #pragma unroll
                for (int j = 0; j < 4; j++)
                    acc[i][j] = fmaf(av[i], bv[j], acc[i][j]);
        }
        __syncthreads();
    }
    #pragma unroll
    for (int i = 0; i < 8; i++) {
        int r = bm + ty * 8 + i;
        if (r < M) {
            float4 o = make_float4(acc[i][0], acc[i][1], acc[i][2], acc[i][3]);
            *(float4*)&g_mx[(size_t)r * DIM + bn + tx * 4] = o;
        }
    }
}

// ---------------- per-row: HypLinear tail + logmap0 -> g_xt ----------------
__global__ void row_k(int layer) {
    __shared__ float red[8];
    int i = blockIdx.x, t = threadIdx.x;
    float hx = g_h [i * DIM + t];
    float mx = g_mx[i * DIM + t];

    float x2s = bsum256(hx * hx, red);
    float x_norm = fmaxf(sqrtf(x2s), MIN_NORM);
    float m2s = bsum256(mx * mx, red);
    float res;
    if (m2s == 0.0f) {
        res = 0.0f;
    } else {
        float mxn = fmaxf(sqrtf(m2s), MIN_NORM);
        res = tanhf(mxn / x_norm * artanh_clip(x_norm)) * mx / mxn;
    }
    float s = bsum256(res * res, red);
    float n = fmaxf(sqrtf(s), MIN_NORM);
    if (n > MAXNORM) res *= MAXNORM / n;

    float y  = g_bias[layer][t];
    float y2 = bsum256(y * y, red);
    float x2 = bsum256(res * res, red);
    float xy = bsum256(res * y, red);
    float num = (1.0f + 2.0f * xy + y2) * res + (1.0f - x2) * y;
    float den = fmaxf(1.0f + 2.0f * xy + x2 * y2, MIN_NORM);
    float hv = num / den;
    s = bsum256(hv * hv, red);
    n = fmaxf(sqrtf(s), MIN_NORM);
    if (n > MAXNORM) hv *= MAXNORM / n;

    s = bsum256(hv * hv, red);
    n = fmaxf(sqrtf(s), MIN_NORM);
    float xt = artanh_clip(n) * hv / n;
    g_xt[i * DIM + t] = xt;
}

// ---------------- aggregation + HypAgg/HypAct tails ----------------
__global__ void agg_k(float* __restrict__ out_opt) {
    __shared__ float red[8];
    __shared__ int   ssrc[128];
    __shared__ float swt [128];
    int i = blockIdx.x, t = threadIdx.x;
    int start = g_rowptr[i], end = g_rowptr[i + 1];
    float acc = 0.0f;

    for (int base = start; base < end; base += 128) {
        int cnt = min(128, end - base);
        if (t < cnt) { ssrc[t] = g_ssrc[base + t]; swt[t] = g_sw[base + t]; }
        __syncthreads();
        int j = 0;
        for (; j + 4 <= cnt; j += 4) {
            float v0 = g_xt[(size_t)ssrc[j + 0] * DIM + t];
            float v1 = g_xt[(size_t)ssrc[j + 1] * DIM + t];
            float v2 = g_xt[(size_t)ssrc[j + 2] * DIM + t];
            float v3 = g_xt[(size_t)ssrc[j + 3] * DIM + t];
            acc = fmaf(swt[j + 0], v0, acc);
            acc = fmaf(swt[j + 1], v1, acc);
            acc = fmaf(swt[j + 2], v2, acc);
            acc = fmaf(swt[j + 3], v3, acc);
        }
        for (; j < cnt; j++)
            acc = fmaf(swt[j], g_xt[(size_t)ssrc[j] * DIM + t], acc);
        __syncthreads();
    }

    float a = acc;
    float s = bsum256(a * a, red);
    float n = fmaxf(sqrtf(s), MIN_NORM);
    a *= tanhf(n) / n;                          // expmap0
    s = bsum256(a * a, red);
    n = fmaxf(sqrtf(s), MIN_NORM);
    if (n > MAXNORM) a *= MAXNORM / n;          // proj
    s = bsum256(a * a, red);
    n = fmaxf(sqrtf(s), MIN_NORM);
    a *= artanh_clip(n) / n;                    // logmap0
    a = fmaxf(a, 0.0f);                         // relu
    s = bsum256(a * a, red);
    n = fmaxf(sqrtf(s), MIN_NORM);
    a *= tanhf(n) / n;                          // expmap0
    s = bsum256(a * a, red);
    n = fmaxf(sqrtf(s), MIN_NORM);
    if (n > MAXNORM) a *= MAXNORM / n;          // proj

    float* o = out_opt ? out_opt : g_h;
    o[i * DIM + t] = a;
}

// ---------------- launch ----------------
extern "C" void kernel_launch(void* const* d_in, const int* in_sizes, int n_in,
                              void* d_out, int out_size) {
    const float* x    = (const float*)d_in[0];
    const float* W1   = (const float*)d_in[1];
    const float* b1   = (const float*)d_in[2];
    const float* W2   = (const float*)d_in[3];
    const float* b2   = (const float*)d_in[4];
    const float* ew   = (const float*)d_in[5];
    const int*   esrc = (const int*)d_in[6];
    const int*   edst = (const int*)d_in[7];
    float*       out  = (float*)d_out;

    int n = in_sizes[0] / DIM;   // 10000
    int E = in_sizes[5];         // 320000

    zero_cnt_k<<<(n + 255) / 256, 256>>>(n);
    hist_k<<<(E + 255) / 256, 256>>>(edst, E);
    scan_k<<<1, 1024>>>(n);
    fill_k<<<(E + 255) / 256, 256>>>(esrc, edst, ew, E);

    bias_k<<<2, DIM>>>(b1, b2);
    init_k<<<n, DIM>>>(x);

    dim3 gg((n + BM - 1) / BM, DIM / BN);

    // layer 1
    gemm_k<<<gg, 256>>>(W1, n);
    row_k<<<n, DIM>>>(0);
    agg_k<<<n, DIM>>>(nullptr);

    // layer 2
    gemm_k<<<gg, 256>>>(W2, n);
    row_k<<<n, DIM>>>(1);
    agg_k<<<n, DIM>>>(out);
}

// round 3
// speedup vs baseline: 1.0575x; 1.0575x over previous
#include <cuda_runtime.h>
#include <cuda_bf16.h>

#define N_NODES 10000
#define DIM     256
#define E_MAX   320000

#define MIN_NORM 1e-15f
#define MAXNORM  0.996f   // (1 - 4e-3)/sqrt(c), c = 1

// ---------------- device scratch (no allocations allowed) ----------------
__device__ float g_h [N_NODES * DIM];   // current hyperbolic features
__device__ float g_xt[N_NODES * DIM];   // tangent features for aggregation
__device__ float g_x2[N_NODES];         // sum-of-squares of each g_h row
__device__ int   g_cnt[N_NODES];
__device__ int   g_rowptr[N_NODES + 1];
__device__ int   g_cursor[N_NODES];
__device__ int   g_ssrc[E_MAX];
__device__ float g_sw[E_MAX];
__device__ float g_bias[2][DIM];
__device__ float g_by2[2];              // sumsq of hyp_bias per layer

// ---------------- helpers ----------------
__device__ __forceinline__ float artanh_clip(float x) {
    x = fminf(fmaxf(x, -1.0f + 1e-7f), 1.0f - 1e-7f);
    return atanhf(x);
}

// block-wide sum over 256 threads; every thread gets the same result
__device__ __forceinline__ float bsum256(float v, float* red) {
    #pragma unroll
    for (int o = 16; o > 0; o >>= 1) v += __shfl_xor_sync(0xffffffffu, v, o);
    if ((threadIdx.x & 31) == 0) red[threadIdx.x >> 5] = v;
    __syncthreads();
    float r = red[0] + red[1] + red[2] + red[3] + red[4] + red[5] + red[6] + red[7];
    __syncthreads();
    return r;
}

// warp-wide sum, all lanes get result
__device__ __forceinline__ float wsum(float v) {
    #pragma unroll
    for (int o = 16; o > 0; o >>= 1) v += __shfl_xor_sync(0xffffffffu, v, o);
    return v;
}

// ---------------- CSR build ----------------
__global__ void zero_cnt_k(int n) {
    int i = blockIdx.x * blockDim.x + threadIdx.x;
    if (i < n) g_cnt[i] = 0;
}

__global__ void hist_k(const int* __restrict__ dst, int E) {
    int base = blockIdx.x * blockDim.x * 4 + threadIdx.x;
    #pragma unroll
    for (int u = 0; u < 4; u++) {
        int e = base + u * blockDim.x;
        if (e < E) atomicAdd(&g_cnt[dst[e]], 1);
    }
}

// single-pass scan: 1024 threads x 10 items covers n <= 10240
__global__ void scan_k(int n) {
    const int IT = 10;
    __shared__ int wsums[32];
    int t = threadIdx.x, lane = t & 31, wid = t >> 5;
    int base = t * IT;
    int v[IT];
    int s = 0;
    #pragma unroll
    for (int i = 0; i < IT; i++) {
        int idx = base + i;
        v[i] = (idx < n) ? g_cnt[idx] : 0;
        s += v[i];
    }
    int x = s;
    #pragma unroll
    for (int o = 1; o < 32; o <<= 1) {
        int y = __shfl_up_sync(0xffffffffu, x, o);
        if (lane >= o) x += y;
    }
    if (lane == 31) wsums[wid] = x;
    __syncthreads();
    if (wid == 0) {
        int w = wsums[lane];
        #pragma unroll
        for (int o = 1; o < 32; o <<= 1) {
            int y = __shfl_up_sync(0xffffffffu, w, o);
            if (lane >= o) w += y;
        }
        wsums[lane] = w;
    }
    __syncthreads();
    int excl = x - s + ((wid > 0) ? wsums[wid - 1] : 0);
    int run = excl;
    #pragma unroll
    for (int i = 0; i < IT; i++) {
        int idx = base + i;
        if (idx < n) { g_rowptr[idx] = run; g_cursor[idx] = run; }
        run += v[i];
    }
    if (t == 1023) g_rowptr[n] = run;
}

__global__ void fill_k(const int* __restrict__ src, const int* __restrict__ dst,
                       const float* __restrict__ w, int E) {
    int base = blockIdx.x * blockDim.x * 4 + threadIdx.x;
    #pragma unroll
    for (int u = 0; u < 4; u++) {
        int e = base + u * blockDim.x;
        if (e < E) {
            int p = atomicAdd(&g_cursor[dst[e]], 1);
            g_ssrc[p] = src[e];
            g_sw[p]   = w[e];
        }
    }
}

// ---------------- hyp_bias = proj(expmap0(b)), store sumsq ----------------
__global__ void bias_k(const float* __restrict__ b1, const float* __restrict__ b2) {
    __shared__ float red[8];
    const float* b = blockIdx.x ? b2 : b1;
    int t = threadIdx.x;
    float v = b[t];
    float s = bsum256(v * v, red);
    float n = fmaxf(sqrtf(s), MIN_NORM);
    v *= tanhf(n) / n;                         // expmap0
    s = bsum256(v * v, red);
    n = fmaxf(sqrtf(s), MIN_NORM);
    if (n > MAXNORM) v *= MAXNORM / n;         // proj
    g_bias[blockIdx.x][t] = v;
    s = bsum256(v * v, red);                   // y2 for mobius_add
    if (t == 0) g_by2[blockIdx.x] = s;
}

// ---------------- h0 = proj(expmap0(x)), store sumsq ----------------
__global__ void init_k(const float* __restrict__ x) {
    __shared__ float red[8];
    int i = blockIdx.x, t = threadIdx.x;
    float v = x[i * DIM + t];
    float s = bsum256(v * v, red);
    float n = fmaxf(sqrtf(s), MIN_NORM);
    v *= tanhf(n) / n;
    s = bsum256(v * v, red);
    n = fmaxf(sqrtf(s), MIN_NORM);
    if (n > MAXNORM) v *= MAXNORM / n;
    g_h[i * DIM + t] = v;
    s = bsum256(v * v, red);
    if (t == 0) g_x2[i] = s;
}

// ---------------- fused GEMM + HypLinear tail + logmap0 -> g_xt ----------
// mx = h @ W^T over full 256-wide rows; each warp owns complete rows so all
// per-row norms are warp shuffle reductions.
#define GBM 32
#define GBK 16
__global__ __launch_bounds__(256) void gemm_fused_k(const float* __restrict__ W,
                                                    int layer, int M) {
    __shared__ float As[GBK][GBM + 1];
    __shared__ float Bs[GBK][DIM + 1];
    int tid = threadIdx.x;
    int bm  = blockIdx.x * GBM;
    int tx  = tid & 31;        // lane
    int ty  = tid >> 5;        // warp 0..7: rows bm+ty*4 .. +3

    float acc[4][8];
    #pragma unroll
    for (int i = 0; i < 4; i++)
        #pragma unroll
        for (int j = 0; j < 8; j++) acc[i][j] = 0.0f;

    // load addresses
    int a_r = tid >> 3;            // 0..31
    int a_k = (tid & 7) * 2;       // 0,2,..,14
    int b_j = tid >> 2;            // 0..63 (+64q)
    int b_k = (tid & 3) * 4;       // 0,4,8,12

    for (int k0 = 0; k0 < DIM; k0 += GBK) {
        // A tile: 32 rows x 16 k
        {
            int r = bm + a_r;
            float2 v = make_float2(0.f, 0.f);
            if (r < M) v = *(const float2*)&g_h[(size_t)r * DIM + k0 + a_k];
            As[a_k + 0][a_r] = v.x;
            As[a_k + 1][a_r] = v.y;
        }
        // B tile: 256 cols x 16 k (W row-major [j][k])
        #pragma unroll
        for (int q = 0; q < 4; q++) {
            int j = b_j + 64 * q;
            float4 v = *(const float4*)&W[(size_t)j * DIM + k0 + b_k];
            Bs[b_k + 0][j] = v.x;
            Bs[b_k + 1][j] = v.y;
            Bs[b_k + 2][j] = v.z;
            Bs[b_k + 3][j] = v.w;
        }
        __syncthreads();
        #pragma unroll
        for (int k = 0; k < GBK; k++) {
            float a0 = As[k][ty * 4 + 0];
            float a1 = As[k][ty * 4 + 1];
            float a2 = As[k][ty * 4 + 2];
            float a3 = As[k][ty * 4 + 3];
            float b[8];
            #pragma unroll
            for (int j = 0; j < 8; j++) b[j] = Bs[k][tx + 32 * j];
            #pragma unroll
            for (int j = 0; j < 8; j++) {
                acc[0][j] = fmaf(a0, b[j], acc[0][j]);
                acc[1][j] = fmaf(a1, b[j], acc[1][j]);
                acc[2][j] = fmaf(a2, b[j], acc[2][j]);
                acc[3][j] = fmaf(a3, b[j], acc[3][j]);
            }
        }
        __syncthreads();
    }

    // ---- epilogue: per-row HypLinear tail, warp-local ----
    float y[8];
    #pragma unroll
    for (int j = 0; j < 8; j++) y[j] = g_bias[layer][tx + 32 * j];
    float y2 = g_by2[layer];

    #pragma unroll
    for (int i = 0; i < 4; i++) {
        int row = bm + ty * 4 + i;
        if (row >= M) continue;

        float msq = 0.0f;
        #pragma unroll
        for (int j = 0; j < 8; j++) msq = fmaf(acc[i][j], acc[i][j], msq);
        float m2s = wsum(msq);

        float res[8];
        if (m2s == 0.0f) {
            #pragma unroll
            for (int j = 0; j < 8; j++) res[j] = 0.0f;
        } else {
            float x_norm = fmaxf(sqrtf(g_x2[row]), MIN_NORM);
            float mxn = fmaxf(sqrtf(m2s), MIN_NORM);
            float sc = tanhf(mxn / x_norm * artanh_clip(x_norm)) / mxn;
            #pragma unroll
            for (int j = 0; j < 8; j++) res[j] = acc[i][j] * sc;
        }
        // proj(res)
        float p = 0.0f;
        #pragma unroll
        for (int j = 0; j < 8; j++) p = fmaf(res[j], res[j], p);
        float n = fmaxf(sqrtf(wsum(p)), MIN_NORM);
        if (n > MAXNORM) {
            float sc = MAXNORM / n;
            #pragma unroll
            for (int j = 0; j < 8; j++) res[j] *= sc;
        }
        // mobius_add(res, hyp_bias)
        float px = 0.0f, pxy = 0.0f;
        #pragma unroll
        for (int j = 0; j < 8; j++) {
            px  = fmaf(res[j], res[j], px);
            pxy = fmaf(res[j], y[j],   pxy);
        }
        float x2 = wsum(px);
        float xy = wsum(pxy);
        float ca  = 1.0f + 2.0f * xy + y2;
        float cb  = 1.0f - x2;
        float den = fmaxf(1.0f + 2.0f * xy + x2 * y2, MIN_NORM);
        float inv = 1.0f / den;
        float hv[8];
        #pragma unroll
        for (int j = 0; j < 8; j++) hv[j] = (ca * res[j] + cb * y[j]) * inv;
        // proj(hv)
        p = 0.0f;
        #pragma unroll
        for (int j = 0; j < 8; j++) p = fmaf(hv[j], hv[j], p);
        n = fmaxf(sqrtf(wsum(p)), MIN_NORM);
        if (n > MAXNORM) {
            float sc = MAXNORM / n;
            #pragma unroll
            for (int j = 0; j < 8; j++) hv[j] *= sc;
        }
        // logmap0(hv)
        p = 0.0f;
        #pragma unroll
        for (int j = 0; j < 8; j++) p = fmaf(hv[j], hv[j], p);
        float pn = fmaxf(sqrtf(wsum(p)), MIN_NORM);
        float ls = artanh_clip(pn) / pn;
        #pragma unroll
        for (int j = 0; j < 8; j++)
            g_xt[(size_t)row * DIM + tx + 32 * j] = hv[j] * ls;
    }
}

// ---------------- aggregation + HypAgg/HypAct tails ----------------
__global__ void agg_k(float* __restrict__ out_opt) {
    __shared__ float red[8];
    __shared__ int   ssrc[128];
    __shared__ float swt [128];
    int i = blockIdx.x, t = threadIdx.x;
    int start = g_rowptr[i], end = g_rowptr[i + 1];
    float acc = 0.0f;

    for (int base = start; base < end; base += 128) {
        int cnt = min(128, end - base);
        if (t < cnt) { ssrc[t] = g_ssrc[base + t]; swt[t] = g_sw[base + t]; }
        __syncthreads();
        int j = 0;
        for (; j + 4 <= cnt; j += 4) {
            float v0 = g_xt[(size_t)ssrc[j + 0] * DIM + t];
            float v1 = g_xt[(size_t)ssrc[j + 1] * DIM + t];
            float v2 = g_xt[(size_t)ssrc[j + 2] * DIM + t];
            float v3 = g_xt[(size_t)ssrc[j + 3] * DIM + t];
            acc = fmaf(swt[j + 0], v0, acc);
            acc = fmaf(swt[j + 1], v1, acc);
            acc = fmaf(swt[j + 2], v2, acc);
            acc = fmaf(swt[j + 3], v3, acc);
        }
        for (; j < cnt; j++)
            acc = fmaf(swt[j], g_xt[(size_t)ssrc[j] * DIM + t], acc);
        __syncthreads();
    }

    float a = acc;
    float s = bsum256(a * a, red);
    float n = fmaxf(sqrtf(s), MIN_NORM);
    a *= tanhf(n) / n;                          // expmap0
    s = bsum256(a * a, red);
    n = fmaxf(sqrtf(s), MIN_NORM);
    if (n > MAXNORM) a *= MAXNORM / n;          // proj
    s = bsum256(a * a, red);
    n = fmaxf(sqrtf(s), MIN_NORM);
    a *= artanh_clip(n) / n;                    // logmap0
    a = fmaxf(a, 0.0f);                         // relu
    s = bsum256(a * a, red);
    n = fmaxf(sqrtf(s), MIN_NORM);
    a *= tanhf(n) / n;                          // expmap0
    s = bsum256(a * a, red);
    n = fmaxf(sqrtf(s), MIN_NORM);
    if (n > MAXNORM) a *= MAXNORM / n;          // proj

    float* o = out_opt ? out_opt : g_h;
    o[i * DIM + t] = a;
    s = bsum256(a * a, red);                    // sumsq for next layer x_norm
    if (t == 0) g_x2[i] = s;
}

// ---------------- launch ----------------
extern "C" void kernel_launch(void* const* d_in, const int* in_sizes, int n_in,
                              void* d_out, int out_size) {
    const float* x    = (const float*)d_in[0];
    const float* W1   = (const float*)d_in[1];
    const float* b1   = (const float*)d_in[2];
    const float* W2   = (const float*)d_in[3];
    const float* b2   = (const float*)d_in[4];
    const float* ew   = (const float*)d_in[5];
    const int*   esrc = (const int*)d_in[6];
    const int*   edst = (const int*)d_in[7];
    float*       out  = (float*)d_out;

    int n = in_sizes[0] / DIM;   // 10000
    int E = in_sizes[5];         // 320000

    zero_cnt_k<<<(n + 255) / 256, 256>>>(n);
    hist_k<<<(E + 1023) / 1024, 256>>>(edst, E);
    scan_k<<<1, 1024>>>(n);
    fill_k<<<(E + 1023) / 1024, 256>>>(esrc, edst, ew, E);

    bias_k<<<2, DIM>>>(b1, b2);
    init_k<<<n, DIM>>>(x);

    int gblocks = (n + GBM - 1) / GBM;

    // layer 1
    gemm_fused_k<<<gblocks, 256>>>(W1, 0, n);
    agg_k<<<n, DIM>>>(nullptr);

    // layer 2
    gemm_fused_k<<<gblocks, 256>>>(W2, 1, n);
    agg_k<<<n, DIM>>>(out);
}

// round 5
// speedup vs baseline: 1.0944x; 1.0349x over previous
#include <cuda_runtime.h>
#include <cuda_bf16.h>
#include <cstdint>

#define N_NODES 10000
#define DIM     256
#define E_MAX   320000

#define MIN_NORM 1e-15f
#define MAXNORM  0.996f   // (1 - 4e-3)/sqrt(c), c = 1

// ---------------- device scratch (no allocations allowed) ----------------
__device__ float g_h [N_NODES * DIM];   // current hyperbolic features
__device__ float g_xt[N_NODES * DIM];   // tangent features for aggregation
__device__ float g_x2[N_NODES];         // sum-of-squares of each g_h row
__device__ int   g_cnt[N_NODES];
__device__ int   g_rowptr[N_NODES + 1];
__device__ int   g_cursor[N_NODES];
__device__ int   g_ssrc[E_MAX];
__device__ float g_sw[E_MAX];
__device__ float g_bias[2][DIM];
__device__ float g_by2[2];              // sumsq of hyp_bias per layer

// ---------------- packed f32x2 helpers (sm_100+ PTX, no 'a' needed) ------
typedef unsigned long long u64;

#define FMA2(d, a, b, c) \
    asm("fma.rn.f32x2 %0, %1, %2, %3;" : "=l"(d) : "l"(a), "l"(b), "l"(c))

__device__ __forceinline__ u64 pack_dup(float a) {
    u64 r;
    asm("mov.b64 %0, {%1, %1};" : "=l"(r) : "r"(__float_as_uint(a)));
    return r;
}
__device__ __forceinline__ float lo_f(u64 v) {
    return __uint_as_float((uint32_t)v);
}
__device__ __forceinline__ float hi_f(u64 v) {
    return __uint_as_float((uint32_t)(v >> 32));
}

// ---------------- math helpers ----------------
__device__ __forceinline__ float artanh_clip(float x) {
    x = fminf(fmaxf(x, -1.0f + 1e-7f), 1.0f - 1e-7f);
    return atanhf(x);
}

__device__ __forceinline__ float bsum256(float v, float* red) {
    #pragma unroll
    for (int o = 16; o > 0; o >>= 1) v += __shfl_xor_sync(0xffffffffu, v, o);
    if ((threadIdx.x & 31) == 0) red[threadIdx.x >> 5] = v;
    __syncthreads();
    float r = red[0] + red[1] + red[2] + red[3] + red[4] + red[5] + red[6] + red[7];
    __syncthreads();
    return r;
}

__device__ __forceinline__ float wsum(float v) {
    #pragma unroll
    for (int o = 16; o > 0; o >>= 1) v += __shfl_xor_sync(0xffffffffu, v, o);
    return v;
}

// ---------------- CSR build ----------------
__global__ void zero_cnt_k(int n) {
    int i = blockIdx.x * blockDim.x + threadIdx.x;
    if (i < n) g_cnt[i] = 0;
}

__global__ void hist_k(const int* __restrict__ dst, int E) {
    int base = blockIdx.x * blockDim.x * 4 + threadIdx.x;
    #pragma unroll
    for (int u = 0; u < 4; u++) {
        int e = base + u * blockDim.x;
        if (e < E) atomicAdd(&g_cnt[dst[e]], 1);
    }
}

// single-pass scan: 1024 threads x 10 items covers n <= 10240
__global__ void scan_k(int n) {
    const int IT = 10;
    __shared__ int wsums[32];
    int t = threadIdx.x, lane = t & 31, wid = t >> 5;
    int base = t * IT;
    int v[IT];
    int s = 0;
    #pragma unroll
    for (int i = 0; i < IT; i++) {
        int idx = base + i;
        v[i] = (idx < n) ? g_cnt[idx] : 0;
        s += v[i];
    }
    int x = s;
    #pragma unroll
    for (int o = 1; o < 32; o <<= 1) {
        int y = __shfl_up_sync(0xffffffffu, x, o);
        if (lane >= o) x += y;
    }
    if (lane == 31) wsums[wid] = x;
    __syncthreads();
    if (wid == 0) {
        int w = wsums[lane];
        #pragma unroll
        for (int o = 1; o < 32; o <<= 1) {
            int y = __shfl_up_sync(0xffffffffu, w, o);
            if (lane >= o) w += y;
        }
        wsums[lane] = w;
    }
    __syncthreads();
    int excl = x - s + ((wid > 0) ? wsums[wid - 1] : 0);
    int run = excl;
    #pragma unroll
    for (int i = 0; i < IT; i++) {
        int idx = base + i;
        if (idx < n) { g_rowptr[idx] = run; g_cursor[idx] = run; }
        run += v[i];
    }
    if (t == 1023) g_rowptr[n] = run;
}

__global__ void fill_k(const int* __restrict__ src, const int* __restrict__ dst,
                       const float* __restrict__ w, int E) {
    int base = blockIdx.x * blockDim.x * 4 + threadIdx.x;
    #pragma unroll
    for (int u = 0; u < 4; u++) {
        int e = base + u * blockDim.x;
        if (e < E) {
            int p = atomicAdd(&g_cursor[dst[e]], 1);
            g_ssrc[p] = src[e];
            g_sw[p]   = w[e];
        }
    }
}

// ---------------- hyp_bias = proj(expmap0(b)), store sumsq ----------------
__global__ void bias_k(const float* __restrict__ b1, const float* __restrict__ b2) {
    __shared__ float red[8];
    const float* b = blockIdx.x ? b2 : b1;
    int t = threadIdx.x;
    float v = b[t];
    float s = bsum256(v * v, red);
    float n = fmaxf(sqrtf(s), MIN_NORM);
    v *= tanhf(n) / n;                         // expmap0
    s = bsum256(v * v, red);
    n = fmaxf(sqrtf(s), MIN_NORM);
    if (n > MAXNORM) v *= MAXNORM / n;         // proj
    g_bias[blockIdx.x][t] = v;
    s = bsum256(v * v, red);                   // y2 for mobius_add
    if (t == 0) g_by2[blockIdx.x] = s;
}

// ---------------- h0 = proj(expmap0(x)), store sumsq ----------------
__global__ void init_k(const float* __restrict__ x) {
    __shared__ float red[8];
    int i = blockIdx.x, t = threadIdx.x;
    float v = x[i * DIM + t];
    float s = bsum256(v * v, red);
    float n = fmaxf(sqrtf(s), MIN_NORM);
    v *= tanhf(n) / n;
    s = bsum256(v * v, red);
    n = fmaxf(sqrtf(s), MIN_NORM);
    if (n > MAXNORM) v *= MAXNORM / n;
    g_h[i * DIM + t] = v;
    s = bsum256(v * v, red);
    if (t == 0) g_x2[i] = s;
}

// ---------------- fused GEMM (f32x2) + HypLinear tail -> g_xt ----------
// mx = h @ W^T. BM=64 rows/CTA; 8 warps x 8 rows; lane owns column pairs
// {2*lane + 64*j, +1} so accumulators are packed f32x2 and the per-row norms
// are warp shuffle reductions.
#define GBM 64
#define GBK 16
#define AP  (GBM + 2)
#define BP  (DIM + 2)

__global__ __launch_bounds__(256) void gemm_fused_k(const float* __restrict__ W,
                                                    int layer, int M) {
    __shared__ float As[GBK][AP];
    __shared__ float Bs[GBK][BP];
    int tid = threadIdx.x;
    int bm  = blockIdx.x * GBM;
    int lane = tid & 31;
    int ty   = tid >> 5;       // warp 0..7: rows bm + ty*8 .. +7

    u64 acc[8][4];
    #pragma unroll
    for (int i = 0; i < 8; i++)
        #pragma unroll
        for (int j = 0; j < 4; j++) acc[i][j] = 0ull;

    // load addresses
    int a_r = tid >> 2;            // 0..63
    int a_k = (tid & 3) << 2;      // 0,4,8,12
    int b_j = tid >> 2;            // 0..63 (+64q)

    for (int k0 = 0; k0 < DIM; k0 += GBK) {
        // A tile: 64 rows x 16 k
        {
            int r = bm + a_r;
            float4 v = make_float4(0.f, 0.f, 0.f, 0.f);
            if (r < M) v = *(const float4*)&g_h[(size_t)r * DIM + k0 + a_k];
            As[a_k + 0][a_r] = v.x;
            As[a_k + 1][a_r] = v.y;
            As[a_k + 2][a_r] = v.z;
            As[a_k + 3][a_r] = v.w;
        }
        // B tile: 256 cols x 16 k (W row-major [j][k])
        #pragma unroll
        for (int q = 0; q < 4; q++) {
            int j = b_j + 64 * q;
            float4 v = *(const float4*)&W[(size_t)j * DIM + k0 + a_k];
            Bs[a_k + 0][j] = v.x;
            Bs[a_k + 1][j] = v.y;
            Bs[a_k + 2][j] = v.z;
            Bs[a_k + 3][j] = v.w;
        }
        __syncthreads();
        #pragma unroll
        for (int k = 0; k < GBK; k++) {
            u64 bp[4];
            #pragma unroll
            for (int j = 0; j < 4; j++)
                bp[j] = *(const u64*)&Bs[k][2 * lane + 64 * j];
            #pragma unroll
            for (int i = 0; i < 8; i++) {
                u64 a2 = pack_dup(As[k][ty * 8 + i]);
                #pragma unroll
                for (int j = 0; j < 4; j++)
                    FMA2(acc[i][j], a2, bp[j], acc[i][j]);
            }
        }
        __syncthreads();
    }

    // ---- epilogue: per-row HypLinear tail, warp-local ----
    float y[8];
    #pragma unroll
    for (int j = 0; j < 4; j++) {
        float2 yv = *(const float2*)&g_bias[layer][2 * lane + 64 * j];
        y[2 * j]     = yv.x;
        y[2 * j + 1] = yv.y;
    }
    float y2 = g_by2[layer];

    #pragma unroll
    for (int i = 0; i < 8; i++) {
        int row = bm + ty * 8 + i;
        if (row >= M) continue;

        float mxv[8];
        #pragma unroll
        for (int j = 0; j < 4; j++) {
            mxv[2 * j]     = lo_f(acc[i][j]);
            mxv[2 * j + 1] = hi_f(acc[i][j]);
        }

        float msq = 0.0f;
        #pragma unroll
        for (int j = 0; j < 8; j++) msq = fmaf(mxv[j], mxv[j], msq);
        float m2s = wsum(msq);

        float res[8];
        if (m2s == 0.0f) {
            #pragma unroll
            for (int j = 0; j < 8; j++) res[j] = 0.0f;
        } else {
            float x_norm = fmaxf(sqrtf(g_x2[row]), MIN_NORM);
            float mxn = fmaxf(sqrtf(m2s), MIN_NORM);
            float sc = tanhf(mxn / x_norm * artanh_clip(x_norm)) / mxn;
            #pragma unroll
            for (int j = 0; j < 8; j++) res[j] = mxv[j] * sc;
        }
        // proj(res)
        float p = 0.0f;
        #pragma unroll
        for (int j = 0; j < 8; j++) p = fmaf(res[j], res[j], p);
        float n = fmaxf(sqrtf(wsum(p)), MIN_NORM);
        if (n > MAXNORM) {
            float sc = MAXNORM / n;
            #pragma unroll
            for (int j = 0; j < 8; j++) res[j] *= sc;
        }
        // mobius_add(res, hyp_bias)
        float px = 0.0f, pxy = 0.0f;
        #pragma unroll
        for (int j = 0; j < 8; j++) {
            px  = fmaf(res[j], res[j], px);
            pxy = fmaf(res[j], y[j],   pxy);
        }
        float x2 = wsum(px);
        float xy = wsum(pxy);
        float ca  = 1.0f + 2.0f * xy + y2;
        float cb  = 1.0f - x2;
        float den = fmaxf(1.0f + 2.0f * xy + x2 * y2, MIN_NORM);
        float inv = 1.0f / den;
        float hv[8];
        #pragma unroll
        for (int j = 0; j < 8; j++) hv[j] = (ca * res[j] + cb * y[j]) * inv;
        // proj(hv)
        p = 0.0f;
        #pragma unroll
        for (int j = 0; j < 8; j++) p = fmaf(hv[j], hv[j], p);
        n = fmaxf(sqrtf(wsum(p)), MIN_NORM);
        if (n > MAXNORM) {
            float sc = MAXNORM / n;
            #pragma unroll
            for (int j = 0; j < 8; j++) hv[j] *= sc;
        }
        // logmap0(hv)
        p = 0.0f;
        #pragma unroll
        for (int j = 0; j < 8; j++) p = fmaf(hv[j], hv[j], p);
        float pn = fmaxf(sqrtf(wsum(p)), MIN_NORM);
        float ls = artanh_clip(pn) / pn;
        #pragma unroll
        for (int j = 0; j < 4; j++) {
            float2 o = make_float2(hv[2 * j] * ls, hv[2 * j + 1] * ls);
            *(float2*)&g_xt[(size_t)row * DIM + 2 * lane + 64 * j] = o;
        }
    }
}

// ---------------- aggregation + HypAgg/HypAct tails ----------------
__global__ void agg_k(float* __restrict__ out_opt) {
    __shared__ float red[8];
    __shared__ int   ssrc[128];
    __shared__ float swt [128];
    int i = blockIdx.x, t = threadIdx.x;
    int start = g_rowptr[i], end = g_rowptr[i + 1];
    float acc = 0.0f;

    for (int base = start; base < end; base += 128) {
        int cnt = min(128, end - base);
        if (t < cnt) { ssrc[t] = g_ssrc[base + t]; swt[t] = g_sw[base + t]; }
        __syncthreads();
        int j = 0;
        for (; j + 4 <= cnt; j += 4) {
            float v0 = g_xt[(size_t)ssrc[j + 0] * DIM + t];
            float v1 = g_xt[(size_t)ssrc[j + 1] * DIM + t];
            float v2 = g_xt[(size_t)ssrc[j + 2] * DIM + t];
            float v3 = g_xt[(size_t)ssrc[j + 3] * DIM + t];
            acc = fmaf(swt[j + 0], v0, acc);
            acc = fmaf(swt[j + 1], v1, acc);
            acc = fmaf(swt[j + 2], v2, acc);
            acc = fmaf(swt[j + 3], v3, acc);
        }
        for (; j < cnt; j++)
            acc = fmaf(swt[j], g_xt[(size_t)ssrc[j] * DIM + t], acc);
        __syncthreads();
    }

    float a = acc;
    float s = bsum256(a * a, red);
    float n = fmaxf(sqrtf(s), MIN_NORM);
    a *= tanhf(n) / n;                          // expmap0
    s = bsum256(a * a, red);
    n = fmaxf(sqrtf(s), MIN_NORM);
    if (n > MAXNORM) a *= MAXNORM / n;          // proj
    s = bsum256(a * a, red);
    n = fmaxf(sqrtf(s), MIN_NORM);
    a *= artanh_clip(n) / n;                    // logmap0
    a = fmaxf(a, 0.0f);                         // relu
    s = bsum256(a * a, red);
    n = fmaxf(sqrtf(s), MIN_NORM);
    a *= tanhf(n) / n;                          // expmap0
    s = bsum256(a * a, red);
    n = fmaxf(sqrtf(s), MIN_NORM);
    if (n > MAXNORM) a *= MAXNORM / n;          // proj

    float* o = out_opt ? out_opt : g_h;
    o[i * DIM + t] = a;
    s = bsum256(a * a, red);                    // sumsq for next layer x_norm
    if (t == 0) g_x2[i] = s;
}

// ---------------- launch ----------------
extern "C" void kernel_launch(void* const* d_in, const int* in_sizes, int n_in,
                              void* d_out, int out_size) {
    const float* x    = (const float*)d_in[0];
    const float* W1   = (const float*)d_in[1];
    const float* b1   = (const float*)d_in[2];
    const float* W2   = (const float*)d_in[3];
    const float* b2   = (const float*)d_in[4];
    const float* ew   = (const float*)d_in[5];
    const int*   esrc = (const int*)d_in[6];
    const int*   edst = (const int*)d_in[7];
    float*       out  = (float*)d_out;

    int n = in_sizes[0] / DIM;   // 10000
    int E = in_sizes[5];         // 320000

    zero_cnt_k<<<(n + 255) / 256, 256>>>(n);
    hist_k<<<(E + 1023) / 1024, 256>>>(edst, E);
    scan_k<<<1, 1024>>>(n);
    fill_k<<<(E + 1023) / 1024, 256>>>(esrc, edst, ew, E);

    bias_k<<<2, DIM>>>(b1, b2);
    init_k<<<n, DIM>>>(x);

    int gblocks = (n + GBM - 1) / GBM;   // 157

    // layer 1
    gemm_fused_k<<<gblocks, 256>>>(W1, 0, n);
    agg_k<<<n, DIM>>>(nullptr);

    // layer 2
    gemm_fused_k<<<gblocks, 256>>>(W2, 1, n);
    agg_k<<<n, DIM>>>(out);
}

// round 6
// speedup vs baseline: 1.1003x; 1.0054x over previous
#include <cuda_runtime.h>
#include <cuda_bf16.h>
#include <cuda_fp16.h>
#include <cstdint>

#define N_NODES 10000
#define DIM     256
#define E_MAX   320000

#define MIN_NORM 1e-15f
#define MAXNORM  0.996f   // (1 - 4e-3)/sqrt(c), c = 1

// ---------------- device scratch (no allocations allowed) ----------------
__device__ float  g_h [N_NODES * DIM];   // current hyperbolic features
__device__ __half g_xt[N_NODES * DIM];   // tangent features (fp16)
__device__ float  g_x2[N_NODES];         // sum-of-squares of each g_h row
__device__ int    g_cnt[N_NODES];
__device__ int    g_rowptr[N_NODES + 1];
__device__ int    g_cursor[N_NODES];
__device__ int    g_ssrc[E_MAX];
__device__ float  g_sw[E_MAX];
__device__ float  g_bias[2][DIM];
__device__ float  g_by2[2];              // sumsq of hyp_bias per layer

// ---------------- packed f32x2 helpers (sm_100+ PTX) ------
typedef unsigned long long u64;

#define FMA2(d, a, b, c) \
    asm("fma.rn.f32x2 %0, %1, %2, %3;" : "=l"(d) : "l"(a), "l"(b), "l"(c))

__device__ __forceinline__ u64 pack_dup(float a) {
    u64 r;
    asm("mov.b64 %0, {%1, %1};" : "=l"(r) : "r"(__float_as_uint(a)));
    return r;
}
__device__ __forceinline__ float lo_f(u64 v) {
    return __uint_as_float((uint32_t)v);
}
__device__ __forceinline__ float hi_f(u64 v) {
    return __uint_as_float((uint32_t)(v >> 32));
}

// ---------------- math helpers ----------------
__device__ __forceinline__ float artanh_clip(float x) {
    x = fminf(fmaxf(x, -1.0f + 1e-7f), 1.0f - 1e-7f);
    return atanhf(x);
}

__device__ __forceinline__ float bsum256(float v, float* red) {
    #pragma unroll
    for (int o = 16; o > 0; o >>= 1) v += __shfl_xor_sync(0xffffffffu, v, o);
    if ((threadIdx.x & 31) == 0) red[threadIdx.x >> 5] = v;
    __syncthreads();
    float r = red[0] + red[1] + red[2] + red[3] + red[4] + red[5] + red[6] + red[7];
    __syncthreads();
    return r;
}

__device__ __forceinline__ float wsum(float v) {
    #pragma unroll
    for (int o = 16; o > 0; o >>= 1) v += __shfl_xor_sync(0xffffffffu, v, o);
    return v;
}

// ---------------- CSR build ----------------
__global__ void hist_k(const int* __restrict__ dst, int E) {
    int base = blockIdx.x * blockDim.x * 4 + threadIdx.x;
    #pragma unroll
    for (int u = 0; u < 4; u++) {
        int e = base + u * blockDim.x;
        if (e < E) atomicAdd(&g_cnt[dst[e]], 1);
    }
}

// single-pass scan: 1024 threads x 10 items covers n <= 10240
__global__ void scan_k(int n) {
    const int IT = 10;
    __shared__ int wsums[32];
    int t = threadIdx.x, lane = t & 31, wid = t >> 5;
    int base = t * IT;
    int v[IT];
    int s = 0;
    #pragma unroll
    for (int i = 0; i < IT; i++) {
        int idx = base + i;
        v[i] = (idx < n) ? g_cnt[idx] : 0;
        s += v[i];
    }
    int x = s;
    #pragma unroll
    for (int o = 1; o < 32; o <<= 1) {
        int y = __shfl_up_sync(0xffffffffu, x, o);
        if (lane >= o) x += y;
    }
    if (lane == 31) wsums[wid] = x;
    __syncthreads();
    if (wid == 0) {
        int w = wsums[lane];
        #pragma unroll
        for (int o = 1; o < 32; o <<= 1) {
            int y = __shfl_up_sync(0xffffffffu, w, o);
            if (lane >= o) w += y;
        }
        wsums[lane] = w;
    }
    __syncthreads();
    int excl = x - s + ((wid > 0) ? wsums[wid - 1] : 0);
    int run = excl;
    #pragma unroll
    for (int i = 0; i < IT; i++) {
        int idx = base + i;
        if (idx < n) { g_rowptr[idx] = run; g_cursor[idx] = run; }
        run += v[i];
    }
    if (t == 1023) g_rowptr[n] = run;
}

__global__ void fill_k(const int* __restrict__ src, const int* __restrict__ dst,
                       const float* __restrict__ w, int E) {
    int base = blockIdx.x * blockDim.x * 4 + threadIdx.x;
    #pragma unroll
    for (int u = 0; u < 4; u++) {
        int e = base + u * blockDim.x;
        if (e < E) {
            int p = atomicAdd(&g_cursor[dst[e]], 1);
            g_ssrc[p] = src[e];
            g_sw[p]   = w[e];
        }
    }
}

// ---------------- hyp_bias = proj(expmap0(b)), store sumsq ----------------
__global__ void bias_k(const float* __restrict__ b1, const float* __restrict__ b2) {
    __shared__ float red[8];
    const float* b = blockIdx.x ? b2 : b1;
    int t = threadIdx.x;
    float v = b[t];
    float s = bsum256(v * v, red);
    float n = fmaxf(sqrtf(s), MIN_NORM);
    v *= tanhf(n) / n;                         // expmap0
    s = bsum256(v * v, red);
    n = fmaxf(sqrtf(s), MIN_NORM);
    if (n > MAXNORM) v *= MAXNORM / n;         // proj
    g_bias[blockIdx.x][t] = v;
    s = bsum256(v * v, red);                   // y2 for mobius_add
    if (t == 0) g_by2[blockIdx.x] = s;
}

// ---------------- h0 = proj(expmap0(x)), store sumsq ----------------
__global__ void init_k(const float* __restrict__ x) {
    __shared__ float red[8];
    int i = blockIdx.x, t = threadIdx.x;
    float v = x[i * DIM + t];
    float s = bsum256(v * v, red);
    float n = fmaxf(sqrtf(s), MIN_NORM);
    v *= tanhf(n) / n;
    s = bsum256(v * v, red);
    n = fmaxf(sqrtf(s), MIN_NORM);
    if (n > MAXNORM) v *= MAXNORM / n;
    g_h[i * DIM + t] = v;
    s = bsum256(v * v, red);
    if (t == 0) g_x2[i] = s;
}

// ---------------- fused GEMM (f32x2) + HypLinear tail -> g_xt ----------
// mx = h @ W^T. BM=32 rows/CTA (313 CTAs, 2 CTAs/SM -> no fat tail wave);
// 8 warps x 4 rows; lane owns column pairs {2*lane + 64*j, +1}.
#define GBM 32
#define GBK 16
#define AP  (GBM + 2)
#define BP  (DIM + 2)

__global__ __launch_bounds__(256, 2) void gemm_fused_k(const float* __restrict__ W,
                                                       int layer, int M) {
    __shared__ float As[GBK][AP];
    __shared__ float Bs[GBK][BP];
    int tid = threadIdx.x;
    int bm  = blockIdx.x * GBM;
    int lane = tid & 31;
    int ty   = tid >> 5;       // warp 0..7: rows bm + ty*4 .. +3

    u64 acc[4][4];
    #pragma unroll
    for (int i = 0; i < 4; i++)
        #pragma unroll
        for (int j = 0; j < 4; j++) acc[i][j] = 0ull;

    // load addresses
    int a_r = tid >> 3;            // 0..31
    int a_k = (tid & 7) << 1;      // 0,2,..,14
    int b_j = tid >> 2;            // 0..63 (+64q)
    int b_k = (tid & 3) << 2;      // 0,4,8,12

    for (int k0 = 0; k0 < DIM; k0 += GBK) {
        // A tile: 32 rows x 16 k
        {
            int r = bm + a_r;
            float2 v = make_float2(0.f, 0.f);
            if (r < M) v = *(const float2*)&g_h[(size_t)r * DIM + k0 + a_k];
            As[a_k + 0][a_r] = v.x;
            As[a_k + 1][a_r] = v.y;
        }
        // B tile: 256 cols x 16 k (W row-major [j][k])
        #pragma unroll
        for (int q = 0; q < 4; q++) {
            int j = b_j + 64 * q;
            float4 v = *(const float4*)&W[(size_t)j * DIM + k0 + b_k];
            Bs[b_k + 0][j] = v.x;
            Bs[b_k + 1][j] = v.y;
            Bs[b_k + 2][j] = v.z;
            Bs[b_k + 3][j] = v.w;
        }
        __syncthreads();
        #pragma unroll
        for (int k = 0; k < GBK; k++) {
            u64 bp[4];
            #pragma unroll
            for (int j = 0; j < 4; j++)
                bp[j] = *(const u64*)&Bs[k][2 * lane + 64 * j];
            #pragma unroll
            for (int i = 0; i < 4; i++) {
                u64 a2 = pack_dup(As[k][ty * 4 + i]);
                #pragma unroll
                for (int j = 0; j < 4; j++)
                    FMA2(acc[i][j], a2, bp[j], acc[i][j]);
            }
        }
        __syncthreads();
    }

    // ---- epilogue: per-row HypLinear tail, warp-local ----
    float y[8];
    #pragma unroll
    for (int j = 0; j < 4; j++) {
        float2 yv = *(const float2*)&g_bias[layer][2 * lane + 64 * j];
        y[2 * j]     = yv.x;
        y[2 * j + 1] = yv.y;
    }
    float y2 = g_by2[layer];

    #pragma unroll
    for (int i = 0; i < 4; i++) {
        int row = bm + ty * 4 + i;
        if (row >= M) continue;

        float mxv[8];
        #pragma unroll
        for (int j = 0; j < 4; j++) {
            mxv[2 * j]     = lo_f(acc[i][j]);
            mxv[2 * j + 1] = hi_f(acc[i][j]);
        }

        float msq = 0.0f;
        #pragma unroll
        for (int j = 0; j < 8; j++) msq = fmaf(mxv[j], mxv[j], msq);
        float m2s = wsum(msq);

        float res[8];
        if (m2s == 0.0f) {
            #pragma unroll
            for (int j = 0; j < 8; j++) res[j] = 0.0f;
        } else {
            float x_norm = fmaxf(sqrtf(g_x2[row]), MIN_NORM);
            float mxn = fmaxf(sqrtf(m2s), MIN_NORM);
            float sc = tanhf(mxn / x_norm * artanh_clip(x_norm)) / mxn;
            #pragma unroll
            for (int j = 0; j < 8; j++) res[j] = mxv[j] * sc;
        }
        // proj(res)
        float p = 0.0f;
        #pragma unroll
        for (int j = 0; j < 8; j++) p = fmaf(res[j], res[j], p);
        float n = fmaxf(sqrtf(wsum(p)), MIN_NORM);
        if (n > MAXNORM) {
            float sc = MAXNORM / n;
            #pragma unroll
            for (int j = 0; j < 8; j++) res[j] *= sc;
        }
        // mobius_add(res, hyp_bias)
        float px = 0.0f, pxy = 0.0f;
        #pragma unroll
        for (int j = 0; j < 8; j++) {
            px  = fmaf(res[j], res[j], px);
            pxy = fmaf(res[j], y[j],   pxy);
        }
        float x2 = wsum(px);
        float xy = wsum(pxy);
        float ca  = 1.0f + 2.0f * xy + y2;
        float cb  = 1.0f - x2;
        float den = fmaxf(1.0f + 2.0f * xy + x2 * y2, MIN_NORM);
        float inv = 1.0f / den;
        float hv[8];
        #pragma unroll
        for (int j = 0; j < 8; j++) hv[j] = (ca * res[j] + cb * y[j]) * inv;
        // proj(hv)
        p = 0.0f;
        #pragma unroll
        for (int j = 0; j < 8; j++) p = fmaf(hv[j], hv[j], p);
        n = fmaxf(sqrtf(wsum(p)), MIN_NORM);
        if (n > MAXNORM) {
            float sc = MAXNORM / n;
            #pragma unroll
            for (int j = 0; j < 8; j++) hv[j] *= sc;
        }
        // logmap0(hv)
        p = 0.0f;
        #pragma unroll
        for (int j = 0; j < 8; j++) p = fmaf(hv[j], hv[j], p);
        float pn = fmaxf(sqrtf(wsum(p)), MIN_NORM);
        float ls = artanh_clip(pn) / pn;
        #pragma unroll
        for (int j = 0; j < 4; j++) {
            __half2 o = __floats2half2_rn(hv[2 * j] * ls, hv[2 * j + 1] * ls);
            *(__half2*)&g_xt[(size_t)row * DIM + 2 * lane + 64 * j] = o;
        }
    }
}

// ---------------- aggregation + HypAgg/HypAct tails ----------------
__global__ void agg_k(float* __restrict__ out_opt) {
    __shared__ float red[8];
    __shared__ int   ssrc[128];
    __shared__ float swt [128];
    int i = blockIdx.x, t = threadIdx.x;
    int start = g_rowptr[i], end = g_rowptr[i + 1];
    float acc = 0.0f;

    for (int base = start; base < end; base += 128) {
        int cnt = min(128, end - base);
        if (t < cnt) { ssrc[t] = g_ssrc[base + t]; swt[t] = g_sw[base + t]; }
        __syncthreads();
        int j = 0;
        for (; j + 4 <= cnt; j += 4) {
            float v0 = __half2float(g_xt[(size_t)ssrc[j + 0] * DIM + t]);
            float v1 = __half2float(g_xt[(size_t)ssrc[j + 1] * DIM + t]);
            float v2 = __half2float(g_xt[(size_t)ssrc[j + 2] * DIM + t]);
            float v3 = __half2float(g_xt[(size_t)ssrc[j + 3] * DIM + t]);
            acc = fmaf(swt[j + 0], v0, acc);
            acc = fmaf(swt[j + 1], v1, acc);
            acc = fmaf(swt[j + 2], v2, acc);
            acc = fmaf(swt[j + 3], v3, acc);
        }
        for (; j < cnt; j++)
            acc = fmaf(swt[j], __half2float(g_xt[(size_t)ssrc[j] * DIM + t]), acc);
        __syncthreads();
    }

    float a = acc;
    float s = bsum256(a * a, red);
    float n = fmaxf(sqrtf(s), MIN_NORM);
    a *= tanhf(n) / n;                          // expmap0
    s = bsum256(a * a, red);
    n = fmaxf(sqrtf(s), MIN_NORM);
    if (n > MAXNORM) a *= MAXNORM / n;          // proj
    s = bsum256(a * a, red);
    n = fmaxf(sqrtf(s), MIN_NORM);
    a *= artanh_clip(n) / n;                    // logmap0
    a = fmaxf(a, 0.0f);                         // relu
    s = bsum256(a * a, red);
    n = fmaxf(sqrtf(s), MIN_NORM);
    a *= tanhf(n) / n;                          // expmap0
    s = bsum256(a * a, red);
    n = fmaxf(sqrtf(s), MIN_NORM);
    if (n > MAXNORM) a *= MAXNORM / n;          // proj

    float* o = out_opt ? out_opt : g_h;
    o[i * DIM + t] = a;
    s = bsum256(a * a, red);                    // sumsq for next layer x_norm
    if (t == 0) g_x2[i] = s;
}

// ---------------- launch ----------------
extern "C" void kernel_launch(void* const* d_in, const int* in_sizes, int n_in,
                              void* d_out, int out_size) {
    const float* x    = (const float*)d_in[0];
    const float* W1   = (const float*)d_in[1];
    const float* b1   = (const float*)d_in[2];
    const float* W2   = (const float*)d_in[3];
    const float* b2   = (const float*)d_in[4];
    const float* ew   = (const float*)d_in[5];
    const int*   esrc = (const int*)d_in[6];
    const int*   edst = (const int*)d_in[7];
    float*       out  = (float*)d_out;

    int n = in_sizes[0] / DIM;   // 10000
    int E = in_sizes[5];         // 320000

    void* cnt_ptr = nullptr;
    cudaGetSymbolAddress(&cnt_ptr, g_cnt);
    cudaMemsetAsync(cnt_ptr, 0, n * sizeof(int));

    hist_k<<<(E + 1023) / 1024, 256>>>(edst, E);
    scan_k<<<1, 1024>>>(n);
    fill_k<<<(E + 1023) / 1024, 256>>>(esrc, edst, ew, E);

    bias_k<<<2, DIM>>>(b1, b2);
    init_k<<<n, DIM>>>(x);

    int gblocks = (n + GBM - 1) / GBM;   // 313

    // layer 1
    gemm_fused_k<<<gblocks, 256>>>(W1, 0, n);
    agg_k<<<n, DIM>>>(nullptr);

    // layer 2
    gemm_fused_k<<<gblocks, 256>>>(W2, 1, n);
    agg_k<<<n, DIM>>>(out);
}